// round 13
// baseline (speedup 1.0000x reference)
#include <cuda_runtime.h>
#include <cuda_bf16.h>

#define B_ 32
#define N_ 256
#define TAIL_FR 4

// ---------------------------------------------------------------------------
// Single fused kernel. Grid (N_ + ceil(T/TAIL_FR), B_), 128 threads.
// Barrier-free prologue: source-row loads issued at instruction 0; each warp
// redundantly computes is64 detection and the durations sums (c1 = prefix
// through idx, d = dur[idx], total) over the whole 256-entry row with
// warp-level reductions only. No __syncthreads anywhere.
//   blockIdx.x <  N_  -> segment block (b, idx): stream-store its d frames.
//   blockIdx.x >= N_  -> tail block: 4 frames; mask + zero-fill of the
//                        contiguous inactive sub-range.
// int32/int64 detection: durations < 16, so if int64 every odd 32-bit word of
// the first 512 words is 0 (region in-bounds under both layouts).
// ---------------------------------------------------------------------------
__global__ __launch_bounds__(128) void main_kernel(
    const float4* __restrict__ start,
    const float4* __restrict__ mid,
    const float4* __restrict__ end,
    const void* __restrict__ dur_raw,
    const void* __restrict__ rc_raw,
    float4* __restrict__ out,
    float* __restrict__ mask_out,
    int T, int F4, int write_mask)
{
    const int b    = blockIdx.y;
    const int tid  = threadIdx.x;
    const int lane = tid & 31;
    const bool is_seg = (blockIdx.x < N_);
    const int idx = is_seg ? blockIdx.x : -1;
    const int f0  = tid;

    // ---- hoisted loads: in flight during the whole prologue ----
    float4 s, m, e;
    int cls32 = 0;
    int rb = 0;
    if (is_seg) {
        rb = (b * N_ + idx) * F4 + f0;
        s = __ldg(start + rb);
        m = __ldg(mid + rb);
        e = __ldg(end + rb);
        cls32 = __ldg((const int*)rc_raw + b * N_ + idx);
    }

    // ---- warp-local is64 detection (first 512 words, L1-broadcast-hot) ----
    const int4* d4 = (const int4*)dur_raw;
    int acc = 0;
#pragma unroll
    for (int j = 0; j < 4; ++j) {
        int4 w = __ldg(d4 + lane * 4 + j);
        acc |= w.y | w.w;
    }
    acc = __reduce_or_sync(0xffffffffu, acc);
    const int is64 = (acc == 0) ? 1 : 0;

    // ---- warp-local durations sums over the full 256-entry row ----
    int accC = 0, accD = 0, accT = 0;
    if (is64) {
#pragma unroll
        for (int j = 0; j < 4; ++j) {
            const int i4 = lane * 4 + j;          // int4 index 0..127
            int4 w = __ldg(d4 + b * 128 + i4);
            const int e0 = 2 * i4, e1 = e0 + 1;
            accT += w.x + w.z;
            if (e0 <= idx) accC += w.x;
            if (e1 <= idx) accC += w.z;
            if (e0 == idx) accD += w.x;
            if (e1 == idx) accD += w.z;
        }
    } else {
#pragma unroll
        for (int j = 0; j < 2; ++j) {
            const int i4 = lane * 2 + j;          // int4 index 0..63
            int4 w = __ldg(d4 + b * 64 + i4);
            const int e0 = 4 * i4;
            accT += w.x + w.y + w.z + w.w;
            if (e0 + 0 <= idx) accC += w.x;
            if (e0 + 1 <= idx) accC += w.y;
            if (e0 + 2 <= idx) accC += w.z;
            if (e0 + 3 <= idx) accC += w.w;
            if (e0 + 0 == idx) accD += w.x;
            if (e0 + 1 == idx) accD += w.y;
            if (e0 + 2 == idx) accD += w.z;
            if (e0 + 3 == idx) accD += w.w;
        }
    }
    const int c1     = __reduce_add_sync(0xffffffffu, accC);
    const int d      = __reduce_add_sync(0xffffffffu, accD);
    const int totalF = __reduce_add_sync(0xffffffffu, accT);

    if (!is_seg) {
        // ---- tail / mask block: frames [tb, tb+TAIL_FR) ----
        const int tb = (blockIdx.x - N_) * TAIL_FR;
        int total = totalF; if (total > T) total = T;
        if (write_mask && f0 < TAIL_FR && tb + f0 < T) {
            mask_out[b * T + tb + f0] = (tb + f0 < total) ? 1.0f : 0.0f;
        }
        if (tb + TAIL_FR <= total) return;    // fully active: nothing to zero
        const float4 z = make_float4(0.f, 0.f, 0.f, 0.f);
        const int ob = (b * T + tb) * F4 + f0;
#pragma unroll
        for (int k = 0; k < TAIL_FR; ++k) {
            const int t = tb + k;
            if (t >= total && t < T) __stcs(out + ob + k * F4, z);
        }
        return;
    }

    // ---- segment block ----
    if (d <= 0) return;
    const int off = c1 - d;
    if (off >= T) return;

    const int cls = is64 ? (int)__ldg((const int*)rc_raw + 2 * (b * N_ + idx))
                         : cls32;
    const bool lin = (cls == 1) && (d >= 4);

    int pe = d; if (off + pe > T) pe = T - off;
    const int half = d >> 1;
    int den1 = half - 1;     if (den1 < 1) den1 = 1;
    int den2 = d - half - 1; if (den2 < 1) den2 = 1;
    const float inv1 = 1.0f / (float)den1;
    const float inv2 = 1.0f / (float)den2;

    float4* __restrict__ ob = out + (b * T + off) * F4 + f0;

    if (lin) {
#pragma unroll 4
        for (int p = 0; p < pe; ++p) {
            const bool fh = (p < half);
            const float w1 = fh ? (float)p * inv1 : (float)(p - half) * inv2;
            const float w0 = 1.0f - w1;
            const float4 A  = fh ? s : m;
            const float4 Bv = fh ? m : e;
            float4 r;
            r.x = fmaf(A.x, w0, Bv.x * w1);
            r.y = fmaf(A.y, w0, Bv.y * w1);
            r.z = fmaf(A.z, w0, Bv.z * w1);
            r.w = fmaf(A.w, w0, Bv.w * w1);
            __stcs(ob + p * F4, r);
        }
    } else {
#pragma unroll 4
        for (int p = 0; p < pe; ++p) {
            float4 r = m;
            if (d > 1) {
                if (p == 0)          r = s;
                else if (p == d - 1) r = e;
            }
            __stcs(ob + p * F4, r);
        }
    }
}

// ---------------------------------------------------------------------------
// Launch
// ---------------------------------------------------------------------------
extern "C" void kernel_launch(void* const* d_in, const int* in_sizes, int n_in,
                              void* d_out, int out_size) {
    const float* start = (const float*)d_in[0];
    const float* mid   = (const float*)d_in[1];
    const float* end   = (const float*)d_in[2];
    const void*  dur   = d_in[3];
    const void*  rc    = d_in[4];
    (void)n_in;

    const int BN = in_sizes[3];                 // B*N
    const int F  = in_sizes[0] / BN;            // 512
    const int F4 = F / 4;

    long long os = (long long)out_size;
    int T, write_mask;
    if (os % ((long long)B_ * (F + 1)) == 0) {
        T = (int)(os / ((long long)B_ * (F + 1)));
        write_mask = 1;
    } else {
        T = (int)(os / ((long long)B_ * F));
        write_mask = 0;
    }

    float* out_f  = (float*)d_out;
    float* mask_f = out_f + B_ * T * F;

    const int tail_blocks = (T + TAIL_FR - 1) / TAIL_FR;
    dim3 grid(N_ + tail_blocks, B_);
    main_kernel<<<grid, 128>>>(
        (const float4*)start, (const float4*)mid, (const float4*)end,
        dur, rc, (float4*)out_f, mask_f, T, F4, write_mask);
}

// round 14
// speedup vs baseline: 2.0360x; 2.0360x over previous
#include <cuda_runtime.h>
#include <cuda_bf16.h>

#define B_ 32
#define N_ 256
#define TAIL_FR 8

// ---------------------------------------------------------------------------
// Single fused kernel. Grid (N_ + ceil(T/TAIL_FR), B_), 128 threads.
//   blockIdx.x <  N_  -> segment block (b, idx): block reduction for c1/d,
//                        load <=3 source rows once, stream-store d frames.
//   blockIdx.x >= N_  -> tail block: 8 frames; mask + zero-fill of the
//                        contiguous inactive sub-range.
// Prologue: per-warp int64 detection from the first 32 words only (no smem,
// no barrier; durations < 16 so int64 => odd words all 0, prob 16^-16 of a
// false positive for int32), then ONE block-wide reduction (1 barrier) for
// c1 (prefix through idx), d (dur[idx]) and total.
// All barriers complete before any divergent exit.
// ---------------------------------------------------------------------------
__global__ __launch_bounds__(128) void main_kernel(
    const float4* __restrict__ start,
    const float4* __restrict__ mid,
    const float4* __restrict__ end,
    const void* __restrict__ dur_raw,
    const void* __restrict__ rc_raw,
    float4* __restrict__ out,
    float* __restrict__ mask_out,
    int T, int F4, int write_mask)
{
    const int b    = blockIdx.y;
    const int tid  = threadIdx.x;
    const int lane = tid & 31;
    const bool is_seg = (blockIdx.x < N_);
    const int idx = is_seg ? blockIdx.x : -1;

    __shared__ int shC[4], shD[4], shT[4];

    // ---- per-warp int64 detection: first 32 words (8 int4), no barrier ----
    const int4* d4 = (const int4*)dur_raw;
    int acc = 0;
    if (lane < 8) {
        int4 w = __ldg(d4 + lane);
        acc = w.y | w.w;
    }
    acc = __reduce_or_sync(0xffffffffu, acc);
    const int is64 = (acc == 0) ? 1 : 0;

    // ---- load this batch's durations, predicated accumulate ----
    int accC = 0, accD = 0, accT = 0;
    if (is64) {
        int4 w = __ldg(d4 + b * 128 + tid);
        const int e0 = 2 * tid, e1 = 2 * tid + 1;
        accT = w.x + w.z;
        if (e0 <= idx) accC += w.x;
        if (e1 <= idx) accC += w.z;
        if (e0 == idx) accD += w.x;
        if (e1 == idx) accD += w.z;
    } else if (tid < 64) {
        int4 w = __ldg(d4 + b * 64 + tid);
        const int e0 = 4 * tid;
        accT = w.x + w.y + w.z + w.w;
        if (e0 + 0 <= idx) accC += w.x;
        if (e0 + 1 <= idx) accC += w.y;
        if (e0 + 2 <= idx) accC += w.z;
        if (e0 + 3 <= idx) accC += w.w;
        if (e0 + 0 == idx) accD += w.x;
        if (e0 + 1 == idx) accD += w.y;
        if (e0 + 2 == idx) accD += w.z;
        if (e0 + 3 == idx) accD += w.w;
    }
    accC = __reduce_add_sync(0xffffffffu, accC);
    accD = __reduce_add_sync(0xffffffffu, accD);
    accT = __reduce_add_sync(0xffffffffu, accT);
    if (lane == 0) {
        shC[tid >> 5] = accC; shD[tid >> 5] = accD; shT[tid >> 5] = accT;
    }
    __syncthreads();
    const int c1     = shC[0] + shC[1] + shC[2] + shC[3];
    const int d      = shD[0] + shD[1] + shD[2] + shD[3];
    const int totalF = shT[0] + shT[1] + shT[2] + shT[3];

    const int f0 = tid;

    if (!is_seg) {
        // ---- tail / mask block: frames [tb, tb+TAIL_FR) ----
        const int tb = (blockIdx.x - N_) * TAIL_FR;
        int total = totalF; if (total > T) total = T;
        if (write_mask && f0 < TAIL_FR && tb + f0 < T) {
            mask_out[b * T + tb + f0] = (tb + f0 < total) ? 1.0f : 0.0f;
        }
        if (tb + TAIL_FR <= total) return;    // fully active: nothing to zero
        const float4 z = make_float4(0.f, 0.f, 0.f, 0.f);
        const int ob = (b * T + tb) * F4 + f0;
#pragma unroll
        for (int k = 0; k < TAIL_FR; ++k) {
            const int t = tb + k;
            if (t >= total && t < T) __stcs(out + ob + k * F4, z);
        }
        return;
    }

    // ---- segment block ----
    if (d <= 0) return;
    const int off = c1 - d;
    if (off >= T) return;

    const int cls = is64 ? (int)((const long long*)rc_raw)[b * N_ + idx]
                         : ((const int*)rc_raw)[b * N_ + idx];
    const bool lin = (cls == 1) && (d >= 4);

    const int rb = (b * N_ + idx) * F4 + f0;
    const bool need_s = lin || (d > 1);
    const bool need_e = lin || (d > 1);
    const bool need_m = lin || (d != 2);
    float4 s, m, e;
    if (need_s) s = __ldg(start + rb);
    if (need_m) m = __ldg(mid + rb);
    if (need_e) e = __ldg(end + rb);

    int pe = d; if (off + pe > T) pe = T - off;
    const int half = d >> 1;
    int den1 = half - 1;     if (den1 < 1) den1 = 1;
    int den2 = d - half - 1; if (den2 < 1) den2 = 1;
    const float inv1 = 1.0f / (float)den1;
    const float inv2 = 1.0f / (float)den2;

    float4* __restrict__ ob = out + (b * T + off) * F4 + f0;

    if (lin) {
#pragma unroll 4
        for (int p = 0; p < pe; ++p) {
            const bool fh = (p < half);
            const float w1 = fh ? (float)p * inv1 : (float)(p - half) * inv2;
            const float w0 = 1.0f - w1;
            const float4 A  = fh ? s : m;
            const float4 Bv = fh ? m : e;
            float4 r;
            r.x = fmaf(A.x, w0, Bv.x * w1);
            r.y = fmaf(A.y, w0, Bv.y * w1);
            r.z = fmaf(A.z, w0, Bv.z * w1);
            r.w = fmaf(A.w, w0, Bv.w * w1);
            __stcs(ob + p * F4, r);
        }
    } else {
#pragma unroll 4
        for (int p = 0; p < pe; ++p) {
            float4 r = m;
            if (d > 1) {
                if (p == 0)          r = s;
                else if (p == d - 1) r = e;
            }
            __stcs(ob + p * F4, r);
        }
    }
}

// ---------------------------------------------------------------------------
// Launch
// ---------------------------------------------------------------------------
extern "C" void kernel_launch(void* const* d_in, const int* in_sizes, int n_in,
                              void* d_out, int out_size) {
    const float* start = (const float*)d_in[0];
    const float* mid   = (const float*)d_in[1];
    const float* end   = (const float*)d_in[2];
    const void*  dur   = d_in[3];
    const void*  rc    = d_in[4];
    (void)n_in;

    const int BN = in_sizes[3];                 // B*N
    const int F  = in_sizes[0] / BN;            // 512
    const int F4 = F / 4;

    long long os = (long long)out_size;
    int T, write_mask;
    if (os % ((long long)B_ * (F + 1)) == 0) {
        T = (int)(os / ((long long)B_ * (F + 1)));
        write_mask = 1;
    } else {
        T = (int)(os / ((long long)B_ * F));
        write_mask = 0;
    }

    float* out_f  = (float*)d_out;
    float* mask_f = out_f + B_ * T * F;

    const int tail_blocks = (T + TAIL_FR - 1) / TAIL_FR;
    dim3 grid(N_ + tail_blocks, B_);
    main_kernel<<<grid, 128>>>(
        (const float4*)start, (const float4*)mid, (const float4*)end,
        dur, rc, (float4*)out_f, mask_f, T, F4, write_mask);
}

// round 15
// speedup vs baseline: 2.0373x; 1.0006x over previous
#include <cuda_runtime.h>
#include <cuda_bf16.h>

#define B_ 32
#define N_ 256
#define TAIL_FR 8
#define D_MAX 16

// ---------------------------------------------------------------------------
// Single fused kernel. Grid (N_ + ceil(T/TAIL_FR), B_), 128 threads.
//   blockIdx.x <  N_  -> segment block (b, idx): block reduction for c1/d,
//                        load <=3 source rows once, stream-store d frames
//                        (fully unrolled predicated STG.128 .cs).
//   blockIdx.x >= N_  -> tail block: 8 frames; mask + zero-fill of the
//                        contiguous inactive sub-range (straight-line).
// Prologue: per-warp int64 detection from the first 32 words only (no smem,
// no barrier; durations < 16 so int64 => odd words all 0), then ONE
// block-wide reduction (1 barrier) for c1, d, total.
// All barriers complete before any divergent exit.
// ---------------------------------------------------------------------------
__global__ __launch_bounds__(128) void main_kernel(
    const float4* __restrict__ start,
    const float4* __restrict__ mid,
    const float4* __restrict__ end,
    const void* __restrict__ dur_raw,
    const void* __restrict__ rc_raw,
    float4* __restrict__ out,
    float* __restrict__ mask_out,
    int T, int F4, int write_mask)
{
    const int b    = blockIdx.y;
    const int tid  = threadIdx.x;
    const int lane = tid & 31;
    const bool is_seg = (blockIdx.x < N_);
    const int idx = is_seg ? blockIdx.x : -1;

    __shared__ int shC[4], shD[4], shT[4];

    // ---- per-warp int64 detection: first 32 words (8 int4), no barrier ----
    const int4* d4 = (const int4*)dur_raw;
    int acc = 0;
    if (lane < 8) {
        int4 w = __ldg(d4 + lane);
        acc = w.y | w.w;
    }
    acc = __reduce_or_sync(0xffffffffu, acc);
    const int is64 = (acc == 0) ? 1 : 0;

    // ---- load this batch's durations, predicated accumulate ----
    int accC = 0, accD = 0, accT = 0;
    if (is64) {
        int4 w = __ldg(d4 + b * 128 + tid);
        const int e0 = 2 * tid, e1 = 2 * tid + 1;
        accT = w.x + w.z;
        if (e0 <= idx) accC += w.x;
        if (e1 <= idx) accC += w.z;
        if (e0 == idx) accD += w.x;
        if (e1 == idx) accD += w.z;
    } else if (tid < 64) {
        int4 w = __ldg(d4 + b * 64 + tid);
        const int e0 = 4 * tid;
        accT = w.x + w.y + w.z + w.w;
        if (e0 + 0 <= idx) accC += w.x;
        if (e0 + 1 <= idx) accC += w.y;
        if (e0 + 2 <= idx) accC += w.z;
        if (e0 + 3 <= idx) accC += w.w;
        if (e0 + 0 == idx) accD += w.x;
        if (e0 + 1 == idx) accD += w.y;
        if (e0 + 2 == idx) accD += w.z;
        if (e0 + 3 == idx) accD += w.w;
    }
    accC = __reduce_add_sync(0xffffffffu, accC);
    accD = __reduce_add_sync(0xffffffffu, accD);
    accT = __reduce_add_sync(0xffffffffu, accT);
    if (lane == 0) {
        shC[tid >> 5] = accC; shD[tid >> 5] = accD; shT[tid >> 5] = accT;
    }
    __syncthreads();
    const int c1     = shC[0] + shC[1] + shC[2] + shC[3];
    const int d      = shD[0] + shD[1] + shD[2] + shD[3];
    const int totalF = shT[0] + shT[1] + shT[2] + shT[3];

    const int f0 = tid;

    if (!is_seg) {
        // ---- tail / mask block: frames [tb, tb+TAIL_FR) ----
        const int tb = (blockIdx.x - N_) * TAIL_FR;
        int total = totalF; if (total > T) total = T;
        if (write_mask && f0 < TAIL_FR && tb + f0 < T) {
            __stcs(mask_out + b * T + tb + f0, (tb + f0 < total) ? 1.0f : 0.0f);
        }
        int zs = tb; if (zs < total) zs = total;   // zero range [zs, ze)
        int ze = tb + TAIL_FR; if (ze > T) ze = T;
        const int nz = ze - zs;
        if (nz <= 0) return;
        const float4 z = make_float4(0.f, 0.f, 0.f, 0.f);
        float4* __restrict__ ob = out + (b * T + zs) * F4 + f0;
#pragma unroll
        for (int k = 0; k < TAIL_FR; ++k) {
            if (k < nz) __stcs(ob + k * F4, z);
        }
        return;
    }

    // ---- segment block ----
    if (d <= 0) return;
    const int off = c1 - d;
    if (off >= T) return;

    const int cls = is64 ? (int)((const long long*)rc_raw)[b * N_ + idx]
                         : ((const int*)rc_raw)[b * N_ + idx];
    const bool lin = (cls == 1) && (d >= 4);

    const int rb = (b * N_ + idx) * F4 + f0;
    const bool need_s = lin || (d > 1);
    const bool need_e = lin || (d > 1);
    const bool need_m = lin || (d != 2);
    float4 s, m, e;
    if (need_s) s = __ldg(start + rb);
    if (need_m) m = __ldg(mid + rb);
    if (need_e) e = __ldg(end + rb);

    int pe = d; if (off + pe > T) pe = T - off;
    if (pe > D_MAX) pe = D_MAX;               // d in [0,16): pe <= 15 always
    const int half = d >> 1;
    int den1 = half - 1;     if (den1 < 1) den1 = 1;
    int den2 = d - half - 1; if (den2 < 1) den2 = 1;
    const float inv1 = 1.0f / (float)den1;
    const float inv2 = 1.0f / (float)den2;

    float4* __restrict__ ob = out + (b * T + off) * F4 + f0;

    if (lin) {
#pragma unroll
        for (int p = 0; p < D_MAX; ++p) {
            if (p < pe) {
                const bool fh = (p < half);
                const float w1 = fh ? (float)p * inv1
                                    : (float)(p - half) * inv2;
                const float w0 = 1.0f - w1;
                const float4 A  = fh ? s : m;
                const float4 Bv = fh ? m : e;
                float4 r;
                r.x = fmaf(A.x, w0, Bv.x * w1);
                r.y = fmaf(A.y, w0, Bv.y * w1);
                r.z = fmaf(A.z, w0, Bv.z * w1);
                r.w = fmaf(A.w, w0, Bv.w * w1);
                __stcs(ob + p * F4, r);
            }
        }
    } else {
#pragma unroll
        for (int p = 0; p < D_MAX; ++p) {
            if (p < pe) {
                float4 r = m;
                if (d > 1) {
                    if (p == 0)          r = s;
                    else if (p == d - 1) r = e;
                }
                __stcs(ob + p * F4, r);
            }
        }
    }
}

// ---------------------------------------------------------------------------
// Launch
// ---------------------------------------------------------------------------
extern "C" void kernel_launch(void* const* d_in, const int* in_sizes, int n_in,
                              void* d_out, int out_size) {
    const float* start = (const float*)d_in[0];
    const float* mid   = (const float*)d_in[1];
    const float* end   = (const float*)d_in[2];
    const void*  dur   = d_in[3];
    const void*  rc    = d_in[4];
    (void)n_in;

    const int BN = in_sizes[3];                 // B*N
    const int F  = in_sizes[0] / BN;            // 512
    const int F4 = F / 4;

    long long os = (long long)out_size;
    int T, write_mask;
    if (os % ((long long)B_ * (F + 1)) == 0) {
        T = (int)(os / ((long long)B_ * (F + 1)));
        write_mask = 1;
    } else {
        T = (int)(os / ((long long)B_ * F));
        write_mask = 0;
    }

    float* out_f  = (float*)d_out;
    float* mask_f = out_f + B_ * T * F;

    const int tail_blocks = (T + TAIL_FR - 1) / TAIL_FR;
    dim3 grid(N_ + tail_blocks, B_);
    main_kernel<<<grid, 128>>>(
        (const float4*)start, (const float4*)mid, (const float4*)end,
        dur, rc, (float4*)out_f, mask_f, T, F4, write_mask);
}